// round 7
// baseline (speedup 1.0000x reference)
#include <cuda_runtime.h>

#define BB 1024
#define TT 2048
#define DD 16
#define UU 4
#define HH 128
#define MM 8
#define NT 1024
#define INP 28          // sINt row pitch (floats)
#define HP  132         // sH1 slice / sH2 / sW2T row pitch (floats)
#define W0P 24          // sW0T row pitch (floats)

typedef unsigned long long u64;

__device__ __forceinline__ u64 pk2(float lo, float hi) {
    u64 r; asm("mov.b64 %0, {%1, %2};" : "=l"(r) : "f"(lo), "f"(hi)); return r;
}
__device__ __forceinline__ void upk2(u64 v, float& lo, float& hi) {
    asm("mov.b64 {%0, %1}, %2;" : "=f"(lo), "=f"(hi) : "l"(v));
}
__device__ __forceinline__ u64 ffma2(u64 a, u64 b, u64 c) {
    u64 d; asm("fma.rn.f32x2 %0, %1, %2, %3;" : "=l"(d) : "l"(a), "l"(b), "l"(c)); return d;
}
__device__ __forceinline__ u64 add2(u64 a, u64 b) {
    u64 c; asm("add.rn.f32x2 %0, %1, %2;" : "=l"(c) : "l"(a), "l"(b)); return c;
}
__device__ __forceinline__ float tanh_fast(float x) {
    float y; asm("tanh.approx.f32 %0, %1;" : "=f"(y) : "f"(x)); return y;
}
__device__ __forceinline__ u64 shfl_xor64(u64 v, int mask) {
    unsigned lo = (unsigned)v, hi = (unsigned)(v >> 32);
    lo = __shfl_xor_sync(0xffffffffu, lo, mask);
    hi = __shfl_xor_sync(0xffffffffu, hi, mask);
    return ((u64)hi << 32) | (u64)lo;
}

__global__ void __launch_bounds__(NT, 1)
gnsde_kernel(const float* __restrict__ carry,
             const float* __restrict__ x,
             const float* __restrict__ noise,
             const float* __restrict__ W0,
             const float* __restrict__ b0,
             const float* __restrict__ W1,
             const float* __restrict__ b1,
             const float* __restrict__ W2,
             const float* __restrict__ b2,
             float* __restrict__ out)
{
    __shared__ __align__(16) float sW0T[HH * W0P];   // [j][k] pitch 24
    __shared__ __align__(16) float sW2T[DD * HP];    // [d][k] pitch 132
    __shared__ __align__(16) float sH1[8 * HP];      // [k>>4][(k&15)*8 + m]
    __shared__ __align__(16) float sH2[MM * HP];     // [m][j]
    __shared__ __align__(16) float sINt[MM * INP];   // [m][k]: 0..15=y, 16..19=x_t

    const int tid = threadIdx.x;
    const int b0r = blockIdx.x * MM;

    // L0 / L1 identity: (jj = tid>>3, kq/m0 = tid&7)
    const int jj = tid >> 3;
    const int kq = tid & 7;
    // L2 identity (tid < 512): warp covers 8 (m,d) pairs, lane = pair*4 + kq2
    const int md2 = ((tid & 511) >> 5) * 8 + ((tid & 31) >> 2);
    const int kq2 = tid & 3;
    const int m2  = md2 >> 4;
    const int d2  = md2 & 15;
    const bool l2w = (tid < 512);            // L2 worker
    const bool outw = l2w && (kq2 == 0);     // output lane
    const bool xsw  = (tid >= 512 && tid < 512 + MM);  // x-staging lane

    // ---- persistent registers: W1 column slice (16 floats) ----
    float w1r[16];
#pragma unroll
    for (int kk = 0; kk < 16; ++kk) w1r[kk] = W1[(kq * 16 + kk) * HH + jj];
    const float b0j = b0[jj];
    const float b1v = b1[jj];
    const float b2v = b2[d2];
    float yreg = 0.0f;
    if (outw) yreg = carry[(size_t)(b0r + m2) * DD + d2];

    // ---- stage shared ----
    for (int idx = tid; idx < (DD + UU) * HH; idx += NT) {
        int k = idx >> 7, j = idx & 127;
        sW0T[j * W0P + k] = W0[idx];
    }
    for (int idx = tid; idx < HH * DD; idx += NT) {
        int i = idx >> 4, d = idx & 15;
        sW2T[d * HP + i] = W2[idx];
    }
    if (outw) sINt[m2 * INP + d2] = yreg;
    if (xsw) {
        int m = tid & 7;
        float4 xv = *(const float4*)&x[((size_t)(b0r + m) * TT) * UU];
        *(float4*)&sINt[m * INP + DD] = xv;
    }
    __syncthreads();

    const float alpha = 0.1f;
    const float onema = 0.9f;
    const float sqa   = 0.31622776601683794f;

    for (int t = 0; t < TT; ++t) {
        // ---- prefetch globals ----
        float nz = 0.0f;
        if (outw) nz = noise[((size_t)(b0r + m2) * TT + t) * DD + d2];
        float4 xn = make_float4(0.f, 0.f, 0.f, 0.f);
        const bool xp = xsw && (t + 1 < TT);
        if (xp) xn = *(const float4*)&x[((size_t)(b0r + (tid & 7)) * TT + (t + 1)) * UU];

        // ===== layer 0: thread (jj, m0=kq); k-paired dot, weights from smem =====
        {
            u64 a0 = 0, a1 = 0;
            const float* rp = &sINt[kq * INP];       // m0 = kq
            const float* wp = &sW0T[jj * W0P];
#pragma unroll
            for (int i = 0; i < 5; ++i) {
                ulonglong2 wv = *(const ulonglong2*)&wp[4 * i];
                ulonglong2 hv = *(const ulonglong2*)&rp[4 * i];
                a0 = ffma2(wv.x, hv.x, a0);
                a1 = ffma2(wv.y, hv.y, a1);
            }
            float lo, hi; upk2(add2(a0, a1), lo, hi);
            sH1[(jj >> 4) * HP + (jj & 15) * 8 + kq] = tanh_fast(lo + hi + b0j);
        }
        __syncthreads();

        // ===== layer 1: thread (jj, kq); 1 j, 16-k slice, 8 m =====
        {
            u64 a0 = 0, a1 = 0, a2 = 0, a3 = 0;     // m-pairs 0..3
            const float* hbase = &sH1[kq * HP];
#pragma unroll
            for (int kk = 0; kk < 16; ++kk) {
                ulonglong2 hA = *(const ulonglong2*)&hbase[kk * 8];
                ulonglong2 hB = *(const ulonglong2*)&hbase[kk * 8 + 4];
                u64 wd = pk2(w1r[kk], w1r[kk]);
                a0 = ffma2(wd, hA.x, a0); a1 = ffma2(wd, hA.y, a1);
                a2 = ffma2(wd, hB.x, a2); a3 = ffma2(wd, hB.y, a3);
            }
            // 3-round reduce over 8-way k-split; lane kq<4 ends with m-pair kq&3
            const bool s2 = (kq & 2) != 0;
            u64 k0 = s2 ? a2 : a0, x0 = s2 ? a0 : a2;
            u64 k1 = s2 ? a3 : a1, x1 = s2 ? a1 : a3;
            u64 n0 = add2(k0, shfl_xor64(x0, 2));
            u64 n1 = add2(k1, shfl_xor64(x1, 2));
            const bool s1 = (kq & 1) != 0;
            u64 q  = s1 ? n1 : n0, xs = s1 ? n0 : n1;
            u64 tot = add2(q, shfl_xor64(xs, 1));
            tot = add2(tot, shfl_xor64(tot, 4));
            if (kq < 4) {
                float lo, hi; upk2(tot, lo, hi);
                int m = 2 * (kq & 3);
                sH2[m * HP + jj]       = tanh_fast(lo + b1v);
                sH2[(m + 1) * HP + jj] = tanh_fast(hi + b1v);
            }
        }
        __syncthreads();

        // ===== layer 2 + gate: 16 warps, thread ((m2,d2), kq2) =====
        if (l2w) {
            u64 aA = 0, aB = 0;
            const float* hr = &sH2[m2 * HP + kq2 * 32];
            const float* wr = &sW2T[d2 * HP + kq2 * 32];
#pragma unroll
            for (int i = 0; i < 8; ++i) {
                ulonglong2 hp = *(const ulonglong2*)&hr[4 * i];
                ulonglong2 wp = *(const ulonglong2*)&wr[4 * i];
                aA = ffma2(hp.x, wp.x, aA);
                aB = ffma2(hp.y, wp.y, aB);
            }
            u64 s = add2(aA, aB);
            s = add2(s, shfl_xor64(s, 1));
            s = add2(s, shfl_xor64(s, 2));
            if (kq2 == 0) {
                float lo, hi; upk2(s, lo, hi);
                float mt = lo + hi + b2v;
                float mu = onema * yreg + alpha * mt;
                float yn = mu + sqa * nz;
                size_t base = ((size_t)(b0r + m2) * TT + t) * DD + d2;
                out[base]                          = yn;
                out[base + (size_t)BB * TT * DD]   = mt;
                out[base + 2ull * BB * TT * DD]    = mu;
                yreg = yn;
                sINt[m2 * INP + d2] = yn;
            }
        } else if (xp) {
            int m = tid & 7;
            *(float4*)&sINt[m * INP + DD] = xn;
        }
        __syncthreads();
    }
}

extern "C" void kernel_launch(void* const* d_in, const int* in_sizes, int n_in,
                              void* d_out, int out_size) {
    const float* carry = (const float*)d_in[0];
    const float* x     = (const float*)d_in[1];
    const float* noise = (const float*)d_in[2];
    const float* W0    = (const float*)d_in[3];
    const float* b0    = (const float*)d_in[4];
    const float* W1    = (const float*)d_in[5];
    const float* b1    = (const float*)d_in[6];
    const float* W2    = (const float*)d_in[7];
    const float* b2    = (const float*)d_in[8];
    float* out = (float*)d_out;

    gnsde_kernel<<<BB / MM, NT>>>(carry, x, noise, W0, b0, W1, b1, W2, b2, out);
}

// round 8
// speedup vs baseline: 2.2711x; 2.2711x over previous
#include <cuda_runtime.h>

#define BB 1024
#define TT 2048
#define DD 16
#define UU 4
#define HH 128
#define MM 8
#define NT 512
#define SINP 12         // sIN row pitch (floats): 16B-aligned rows, staggered banks
#define HP  132         // sH1 slice / sH2 / sW2T row pitch (floats)

typedef unsigned long long u64;

__device__ __forceinline__ u64 pk2(float lo, float hi) {
    u64 r; asm("mov.b64 %0, {%1, %2};" : "=l"(r) : "f"(lo), "f"(hi)); return r;
}
__device__ __forceinline__ void upk2(u64 v, float& lo, float& hi) {
    asm("mov.b64 {%0, %1}, %2;" : "=f"(lo), "=f"(hi) : "l"(v));
}
__device__ __forceinline__ u64 ffma2(u64 a, u64 b, u64 c) {
    u64 d; asm("fma.rn.f32x2 %0, %1, %2, %3;" : "=l"(d) : "l"(a), "l"(b), "l"(c)); return d;
}
__device__ __forceinline__ u64 add2(u64 a, u64 b) {
    u64 c; asm("add.rn.f32x2 %0, %1, %2;" : "=l"(c) : "l"(a), "l"(b)); return c;
}
__device__ __forceinline__ float tanh_fast(float x) {
    float y; asm("tanh.approx.f32 %0, %1;" : "=f"(y) : "f"(x)); return y;
}
__device__ __forceinline__ u64 shfl_xor64(u64 v, int mask) {
    unsigned lo = (unsigned)v, hi = (unsigned)(v >> 32);
    lo = __shfl_xor_sync(0xffffffffu, lo, mask);
    hi = __shfl_xor_sync(0xffffffffu, hi, mask);
    return ((u64)hi << 32) | (u64)lo;
}

__global__ void __launch_bounds__(NT, 1)
gnsde_kernel(const float* __restrict__ carry,
             const float* __restrict__ x,
             const float* __restrict__ noise,
             const float* __restrict__ W0,
             const float* __restrict__ b0,
             const float* __restrict__ W1,
             const float* __restrict__ b1,
             const float* __restrict__ W2,
             const float* __restrict__ b2,
             float* __restrict__ out)
{
    __shared__ __align__(16) float sW2T[DD * HP];       // [d][k], pitch 132
    __shared__ __align__(16) float sH1[8 * HP];         // [k>>4][(k&15)*8 + m]
    __shared__ __align__(16) float sH2[MM * HP];        // [m][j]
    __shared__ __align__(16) float sIN[(DD + UU) * SINP]; // [k][m]: rows 0..15=y, 16..19=x_t

    const int tid = threadIdx.x;
    const int b0r = blockIdx.x * MM;

    // layer-0 identity: (j0, kq0) -- 4-way k-split, k-slice of 5
    const int j0  = tid >> 2;
    const int kq0 = tid & 3;
    // layer-1 identity: (jp, kq) -- j-pair, 8-way k-split
    const int jp  = tid >> 3;
    const int kq  = tid & 7;
    // layer-2 identity (tid < 128): (m2, d2)
    const int m2  = (tid >> 4) & 7;
    const int d2  = tid & 15;

    // ---- persistent registers ----
    float w0r[5];
#pragma unroll
    for (int kk = 0; kk < 5; ++kk) w0r[kk] = W0[(kq0 * 5 + kk) * HH + j0];
    float w1r0[16], w1r1[16];
#pragma unroll
    for (int kk = 0; kk < 16; ++kk) {
        w1r0[kk] = W1[(kq * 16 + kk) * HH + 2 * jp];
        w1r1[kk] = W1[(kq * 16 + kk) * HH + 2 * jp + 1];
    }
    const float b0j = b0[j0];
    const float b1v = b1[2 * jp + (kq >> 2)];

    // ---- stage shared ----
    for (int idx = tid; idx < HH * DD; idx += NT) {
        int i = idx >> 4, d = idx & 15;
        sW2T[d * HP + i] = W2[idx];     // W2 is [H][D] row-major
    }
    __shared__ float sb2[DD];
    if (tid < DD) sb2[tid] = b2[tid];

    float yreg = 0.0f;
    if (tid < 128) {
        yreg = carry[(size_t)(b0r + m2) * DD + d2];
        sIN[d2 * SINP + m2] = yreg;
    }
    if (tid >= 504) {
        int m = tid - 504;
        float4 xv = *(const float4*)&x[((size_t)(b0r + m) * TT) * UU];
        sIN[(DD + 0) * SINP + m] = xv.x;
        sIN[(DD + 1) * SINP + m] = xv.y;
        sIN[(DD + 2) * SINP + m] = xv.z;
        sIN[(DD + 3) * SINP + m] = xv.w;
    }
    __syncthreads();

    const float alpha = 0.1f;
    const float onema = 0.9f;
    const float sqa   = 0.31622776601683794f;

    for (int t = 0; t < TT; ++t) {
        // ---- prefetch globals for this step ----
        float nz = 0.0f;
        if (tid < 128) nz = noise[((size_t)(b0r + m2) * TT + t) * DD + d2];
        float4 xn = make_float4(0.f, 0.f, 0.f, 0.f);
        const bool xp = (tid >= 504) && (t + 1 < TT);
        if (xp) xn = *(const float4*)&x[((size_t)(b0r + (tid - 504)) * TT + (t + 1)) * UU];

        // ===== layer 0: thread (j0, kq0); W0 in regs, [k][m] act reads =====
        {
            u64 a0 = 0, a1 = 0, a2 = 0, a3 = 0;
#pragma unroll
            for (int kk = 0; kk < 5; ++kk) {
                const float* rp = &sIN[(kq0 * 5 + kk) * SINP];
                ulonglong2 hA = *(const ulonglong2*)&rp[0];   // m 0..3
                ulonglong2 hB = *(const ulonglong2*)&rp[4];   // m 4..7
                u64 wd = pk2(w0r[kk], w0r[kk]);
                a0 = ffma2(wd, hA.x, a0); a1 = ffma2(wd, hA.y, a1);
                a2 = ffma2(wd, hB.x, a2); a3 = ffma2(wd, hB.y, a3);
            }
            // 2-round index-halving butterfly over kq0; lane kq0 ends with m-pair kq0
            const bool u2 = (kq0 & 2) != 0;
            u64 k0 = u2 ? a2 : a0, s0 = u2 ? a0 : a2;
            u64 k1 = u2 ? a3 : a1, s1 = u2 ? a1 : a3;
            u64 n0 = add2(k0, shfl_xor64(s0, 2));
            u64 n1 = add2(k1, shfl_xor64(s1, 2));
            const bool u1 = (kq0 & 1) != 0;
            u64 q  = u1 ? n1 : n0, s = u1 ? n0 : n1;
            u64 tot = add2(q, shfl_xor64(s, 1));
            tot = add2(tot, pk2(b0j, b0j));
            float lo, hi; upk2(tot, lo, hi);
            *(u64*)&sH1[(j0 >> 4) * HP + (j0 & 15) * 8 + 2 * kq0] =
                pk2(tanh_fast(lo), tanh_fast(hi));
        }
        __syncthreads();

        // ===== layer 1: thread (jp, kq); weights in regs, dense act wavefronts =====
        {
            u64 a0 = 0, a1 = 0, a2 = 0, a3 = 0, a4 = 0, a5 = 0, a6 = 0, a7 = 0;
            const float* hbase = &sH1[kq * HP];
#pragma unroll
            for (int kk = 0; kk < 16; ++kk) {
                ulonglong2 hA = *(const ulonglong2*)&hbase[kk * 8];
                ulonglong2 hB = *(const ulonglong2*)&hbase[kk * 8 + 4];
                u64 wd0 = pk2(w1r0[kk], w1r0[kk]);
                u64 wd1 = pk2(w1r1[kk], w1r1[kk]);
                a0 = ffma2(wd0, hA.x, a0); a1 = ffma2(wd0, hA.y, a1);
                a2 = ffma2(wd0, hB.x, a2); a3 = ffma2(wd0, hB.y, a3);
                a4 = ffma2(wd1, hA.x, a4); a5 = ffma2(wd1, hA.y, a5);
                a6 = ffma2(wd1, hB.x, a6); a7 = ffma2(wd1, hB.y, a7);
            }
            // index-halving butterfly over the 8-way k-split
            const bool u4 = (kq & 4) != 0;
            u64 k0 = u4 ? a4 : a0, s0 = u4 ? a0 : a4;
            u64 k1 = u4 ? a5 : a1, s1 = u4 ? a1 : a5;
            u64 k2 = u4 ? a6 : a2, s2 = u4 ? a2 : a6;
            u64 k3 = u4 ? a7 : a3, s3 = u4 ? a3 : a7;
            u64 n0 = add2(k0, shfl_xor64(s0, 4));
            u64 n1 = add2(k1, shfl_xor64(s1, 4));
            u64 n2 = add2(k2, shfl_xor64(s2, 4));
            u64 n3 = add2(k3, shfl_xor64(s3, 4));
            const bool u2 = (kq & 2) != 0;
            u64 p0k = u2 ? n2 : n0, p0s = u2 ? n0 : n2;
            u64 p1k = u2 ? n3 : n1, p1s = u2 ? n1 : n3;
            u64 p0 = add2(p0k, shfl_xor64(p0s, 2));
            u64 p1 = add2(p1k, shfl_xor64(p1s, 2));
            const bool u1 = (kq & 1) != 0;
            u64 qk = u1 ? p1 : p0, qs = u1 ? p0 : p1;
            u64 tot = add2(qk, shfl_xor64(qs, 1));

            float lo, hi; upk2(tot, lo, hi);
            lo = tanh_fast(lo + b1v);
            hi = tanh_fast(hi + b1v);
            const int jw = 2 * jp + (kq >> 2);
            const int mA = 2 * (kq & 3);
            sH2[mA * HP + jw]       = lo;
            sH2[(mA + 1) * HP + jw] = hi;
        }
        __syncthreads();

        // ===== layer 2 + gate + noise: threads 0..127 = (m2, d2) =====
        if (tid < 128) {
            u64 accA = 0, accB = 0;
            const float* hrow = &sH2[m2 * HP];
            const float* wrow = &sW2T[d2 * HP];
#pragma unroll
            for (int i = 0; i < HH / 4; ++i) {
                ulonglong2 hp = *(const ulonglong2*)&hrow[4 * i];
                ulonglong2 wp = *(const ulonglong2*)&wrow[4 * i];
                accA = ffma2(hp.x, wp.x, accA);
                accB = ffma2(hp.y, wp.y, accB);
            }
            float lo, hi; upk2(add2(accA, accB), lo, hi);
            float mt = lo + hi + sb2[d2];
            float mu = onema * yreg + alpha * mt;
            float yn = mu + sqa * nz;

            size_t base = ((size_t)(b0r + m2) * TT + t) * DD + d2;
            out[base]                        = yn;
            out[base + (size_t)BB * TT * DD] = mt;
            out[base + 2ull * BB * TT * DD]  = mu;

            yreg = yn;
            sIN[d2 * SINP + m2] = yn;      // publish y for next step
        } else if (xp) {
            int m = tid - 504;
            sIN[(DD + 0) * SINP + m] = xn.x;
            sIN[(DD + 1) * SINP + m] = xn.y;
            sIN[(DD + 2) * SINP + m] = xn.z;
            sIN[(DD + 3) * SINP + m] = xn.w;
        }
        __syncthreads();
    }
}

extern "C" void kernel_launch(void* const* d_in, const int* in_sizes, int n_in,
                              void* d_out, int out_size) {
    const float* carry = (const float*)d_in[0];
    const float* x     = (const float*)d_in[1];
    const float* noise = (const float*)d_in[2];
    const float* W0    = (const float*)d_in[3];
    const float* b0    = (const float*)d_in[4];
    const float* W1    = (const float*)d_in[5];
    const float* b1    = (const float*)d_in[6];
    const float* W2    = (const float*)d_in[7];
    const float* b2    = (const float*)d_in[8];
    float* out = (float*)d_out;

    gnsde_kernel<<<BB / MM, NT>>>(carry, x, noise, W0, b0, W1, b1, W2, b2, out);
}

// round 10
// speedup vs baseline: 4.6059x; 2.0280x over previous
#include <cuda_runtime.h>
#include <cstdint>

#define BB 1024
#define TT 2048
#define DD 16
#define UU 4
#define HH 128
#define MM 8
#define NT 256
#define PIT 24          // sIN/sH1/sH2 row pitch (floats): cols 0-7 hi, 8-15 lo
#define PPIT 10         // sPart row pitch

typedef unsigned long long u64;

__device__ __forceinline__ uint32_t tf32r(float v) {
    uint32_t r; asm("cvt.rna.tf32.f32 %0, %1;" : "=r"(r) : "f"(v)); return r;
}
__device__ __forceinline__ void split(float w, uint32_t& hi, uint32_t& lo) {
    hi = tf32r(w);
    lo = tf32r(w - __uint_as_float(hi));
}
__device__ __forceinline__ float tanh_fast(float x) {
    float y; asm("tanh.approx.f32 %0, %1;" : "=f"(y) : "f"(x)); return y;
}
__device__ __forceinline__ void mma8(float* d, uint4 a, uint32_t b0, uint32_t b1) {
    asm volatile(
        "mma.sync.aligned.m16n8k8.row.col.f32.tf32.tf32.f32 "
        "{%0,%1,%2,%3}, {%4,%5,%6,%7}, {%8,%9}, {%0,%1,%2,%3};"
        : "+f"(d[0]), "+f"(d[1]), "+f"(d[2]), "+f"(d[3])
        : "r"(a.x), "r"(a.y), "r"(a.z), "r"(a.w), "r"(b0), "r"(b1));
}
__device__ __forceinline__ u64 pku(uint32_t lo, uint32_t hi) {
    return ((u64)hi << 32) | (u64)lo;
}

__global__ void __launch_bounds__(NT, 1)
gnsde_kernel(const float* __restrict__ carry,
             const float* __restrict__ x,
             const float* __restrict__ noise,
             const float* __restrict__ W0,
             const float* __restrict__ b0,
             const float* __restrict__ W1,
             const float* __restrict__ b1,
             const float* __restrict__ W2,
             const float* __restrict__ b2,
             float* __restrict__ out)
{
    __shared__ __align__(16) float sIN[32 * PIT];    // rows k: 0-15 y, 16-19 x, 20-31 zero
    __shared__ __align__(16) float sH1[HH * PIT];
    __shared__ __align__(16) float sH2[HH * PIT];
    __shared__ __align__(16) float sPart[8 * 16 * PPIT];

    const int tid  = threadIdx.x;
    const int wid  = tid >> 5;
    const int lane = tid & 31;
    const int g    = lane >> 2;      // groupID
    const int tg   = lane & 3;       // threadID_in_group
    const int b0r  = blockIdx.x * MM;

    const int r0 = wid * 16 + g;     // A-fragment rows (j / d)
    const int r1 = r0 + 8;

    // ---- persistent weight fragments (registers) ----
    uint4 A1h[16], A1l[16];
#pragma unroll
    for (int c = 0; c < 16; ++c) {
        int k0 = 8 * c + tg, k1 = k0 + 4;
        split(W1[k0 * HH + r0], A1h[c].x, A1l[c].x);
        split(W1[k0 * HH + r1], A1h[c].y, A1l[c].y);
        split(W1[k1 * HH + r0], A1h[c].z, A1l[c].z);
        split(W1[k1 * HH + r1], A1h[c].w, A1l[c].w);
    }
    uint4 A0h[4], A0l[4];
#pragma unroll
    for (int c = 0; c < 4; ++c) {
        int k0 = 8 * c + tg, k1 = k0 + 4;
        float v0 = (k0 < DD + UU) ? W0[k0 * HH + r0] : 0.0f;
        float v1 = (k0 < DD + UU) ? W0[k0 * HH + r1] : 0.0f;
        float v2 = (k1 < DD + UU) ? W0[k1 * HH + r0] : 0.0f;
        float v3 = (k1 < DD + UU) ? W0[k1 * HH + r1] : 0.0f;
        split(v0, A0h[c].x, A0l[c].x);
        split(v1, A0h[c].y, A0l[c].y);
        split(v2, A0h[c].z, A0l[c].z);
        split(v3, A0h[c].w, A0l[c].w);
    }
    uint4 A2h[2], A2l[2];
#pragma unroll
    for (int i = 0; i < 2; ++i) {
        int c = 2 * wid + i;
        int k0 = 8 * c + tg, k1 = k0 + 4;
        split(W2[k0 * DD + g],     A2h[i].x, A2l[i].x);
        split(W2[k0 * DD + g + 8], A2h[i].y, A2l[i].y);
        split(W2[k1 * DD + g],     A2h[i].z, A2l[i].z);
        split(W2[k1 * DD + g + 8], A2h[i].w, A2l[i].w);
    }
    const float b0a = b0[r0], b0b = b0[r1];
    const float b1a = b1[r0], b1b = b1[r1];

    // reduce-phase identity (tid < 128): m = tid>>4, d = tid&15
    const int mR = tid >> 4;
    const int dR = tid & 15;
    const float b2v = b2[dR];
    float yreg = 0.0f;

    // ---- init shared ----
    for (int i = tid; i < 32 * PIT; i += NT) sIN[i] = 0.0f;
    __syncthreads();
    uint32_t* sINu = (uint32_t*)sIN;
    uint32_t* sH1u = (uint32_t*)sH1;
    uint32_t* sH2u = (uint32_t*)sH2;
    if (tid < 128) {
        yreg = carry[(size_t)(b0r + mR) * DD + dR];
        uint32_t hi, lo; split(yreg, hi, lo);
        sINu[dR * PIT + mR]     = hi;
        sINu[dR * PIT + 8 + mR] = lo;
    }
    if (tid >= 128 && tid < 128 + MM) {
        int m = tid & 7;
        float4 xv = *(const float4*)&x[((size_t)(b0r + m) * TT) * UU];
        float xa[4] = {xv.x, xv.y, xv.z, xv.w};
#pragma unroll
        for (int u = 0; u < 4; ++u) {
            uint32_t hi, lo; split(xa[u], hi, lo);
            sINu[(DD + u) * PIT + m]     = hi;
            sINu[(DD + u) * PIT + 8 + m] = lo;
        }
    }

    const float alpha = 0.1f;
    const float onema = 0.9f;
    const float sqa   = 0.31622776601683794f;

    for (int t = 0; t < TT; ++t) {
        // ---- prefetch globals ----
        float nz = 0.0f;
        if (tid < 128) nz = noise[((size_t)(b0r + mR) * TT + t) * DD + dR];
        float4 xn = make_float4(0.f, 0.f, 0.f, 0.f);
        const bool xp = (tid >= 128 && tid < 128 + MM) && (t + 1 < TT);
        if (xp) xn = *(const float4*)&x[((size_t)(b0r + (tid & 7)) * TT + (t + 1)) * UU];

        __syncthreads();   // (1) y/x writes of prev step -> L0 reads

        // ===== layer 0: D0 = W0^T(16-slice) @ in, 3xTF32 =====
        {
            float P[4] = {0, 0, 0, 0}, Q[4] = {0, 0, 0, 0}, R[4] = {0, 0, 0, 0};
#pragma unroll
            for (int c = 0; c < 4; ++c) {
                int rA = 8 * c + tg, rB = rA + 4;
                uint32_t b0h = sINu[rA * PIT + g];
                uint32_t b1h = sINu[rB * PIT + g];
                uint32_t b0l = sINu[rA * PIT + 8 + g];
                uint32_t b1l = sINu[rB * PIT + 8 + g];
                mma8(P, A0h[c], b0h, b1h);
                mma8(Q, A0l[c], b0h, b1h);
                mma8(R, A0h[c], b0l, b1l);
            }
            float h0 = tanh_fast(P[0] + Q[0] + R[0] + b0a);
            float h1 = tanh_fast(P[1] + Q[1] + R[1] + b0a);
            float h2 = tanh_fast(P[2] + Q[2] + R[2] + b0b);
            float h3 = tanh_fast(P[3] + Q[3] + R[3] + b0b);
            uint32_t hi0, lo0, hi1, lo1, hi2, lo2, hi3, lo3;
            split(h0, hi0, lo0); split(h1, hi1, lo1);
            split(h2, hi2, lo2); split(h3, hi3, lo3);
            *(u64*)&sH1u[r0 * PIT + 2 * tg]     = pku(hi0, hi1);
            *(u64*)&sH1u[r1 * PIT + 2 * tg]     = pku(hi2, hi3);
            *(u64*)&sH1u[r0 * PIT + 8 + 2 * tg] = pku(lo0, lo1);
            *(u64*)&sH1u[r1 * PIT + 8 + 2 * tg] = pku(lo2, lo3);
        }
        __syncthreads();   // (2)

        // ===== layer 1: K=128, 16 chunks, 3xTF32 =====
        {
            float P[4] = {0, 0, 0, 0}, Q[4] = {0, 0, 0, 0}, R[4] = {0, 0, 0, 0};
#pragma unroll
            for (int c = 0; c < 16; ++c) {
                int rA = 8 * c + tg, rB = rA + 4;
                uint32_t b0h = sH1u[rA * PIT + g];
                uint32_t b1h = sH1u[rB * PIT + g];
                uint32_t b0l = sH1u[rA * PIT + 8 + g];
                uint32_t b1l = sH1u[rB * PIT + 8 + g];
                mma8(P, A1h[c], b0h, b1h);
                mma8(Q, A1l[c], b0h, b1h);
                mma8(R, A1h[c], b0l, b1l);
            }
            float h0 = tanh_fast(P[0] + Q[0] + R[0] + b1a);
            float h1 = tanh_fast(P[1] + Q[1] + R[1] + b1a);
            float h2 = tanh_fast(P[2] + Q[2] + R[2] + b1b);
            float h3 = tanh_fast(P[3] + Q[3] + R[3] + b1b);
            uint32_t hi0, lo0, hi1, lo1, hi2, lo2, hi3, lo3;
            split(h0, hi0, lo0); split(h1, hi1, lo1);
            split(h2, hi2, lo2); split(h3, hi3, lo3);
            *(u64*)&sH2u[r0 * PIT + 2 * tg]     = pku(hi0, hi1);
            *(u64*)&sH2u[r1 * PIT + 2 * tg]     = pku(hi2, hi3);
            *(u64*)&sH2u[r0 * PIT + 8 + 2 * tg] = pku(lo0, lo1);
            *(u64*)&sH2u[r1 * PIT + 8 + 2 * tg] = pku(lo2, lo3);
        }
        __syncthreads();   // (3)

        // ===== layer 2: k-split across warps (chunks 2w, 2w+1), 3xTF32 =====
        {
            float P[4] = {0, 0, 0, 0}, Q[4] = {0, 0, 0, 0}, R[4] = {0, 0, 0, 0};
#pragma unroll
            for (int i = 0; i < 2; ++i) {
                int c = 2 * wid + i;
                int rA = 8 * c + tg, rB = rA + 4;
                uint32_t b0h = sH2u[rA * PIT + g];
                uint32_t b1h = sH2u[rB * PIT + g];
                uint32_t b0l = sH2u[rA * PIT + 8 + g];
                uint32_t b1l = sH2u[rB * PIT + 8 + g];
                mma8(P, A2h[i], b0h, b1h);
                mma8(Q, A2l[i], b0h, b1h);
                mma8(R, A2h[i], b0l, b1l);
            }
            float d0 = P[0] + Q[0] + R[0];
            float d1 = P[1] + Q[1] + R[1];
            float d2 = P[2] + Q[2] + R[2];
            float d3 = P[3] + Q[3] + R[3];
            // partial store: rows d = g / g+8, cols m = 2tg, 2tg+1
            *(float2*)&sPart[wid * 160 + g * PPIT + 2 * tg]       = make_float2(d0, d1);
            *(float2*)&sPart[wid * 160 + (g + 8) * PPIT + 2 * tg] = make_float2(d2, d3);
        }
        __syncthreads();   // (4)

        // ===== reduce + gate + outputs: tid<128 = (mR, dR) =====
        if (tid < 128) {
            float s = 0.0f;
#pragma unroll
            for (int w = 0; w < 8; ++w) s += sPart[w * 160 + dR * PPIT + mR];
            float mt = s + b2v;
            float mu = onema * yreg + alpha * mt;
            float yn = mu + sqa * nz;
            size_t base = ((size_t)(b0r + mR) * TT + t) * DD + dR;
            out[base]                        = yn;
            out[base + (size_t)BB * TT * DD] = mt;
            out[base + 2ull * BB * TT * DD]  = mu;
            yreg = yn;
            uint32_t hi, lo; split(yn, hi, lo);
            sINu[dR * PIT + mR]     = hi;
            sINu[dR * PIT + 8 + mR] = lo;
        } else if (xp) {
            int m = tid & 7;
            float xa[4] = {xn.x, xn.y, xn.z, xn.w};
#pragma unroll
            for (int u = 0; u < 4; ++u) {
                uint32_t hi, lo; split(xa[u], hi, lo);
                sINu[(DD + u) * PIT + m]     = hi;
                sINu[(DD + u) * PIT + 8 + m] = lo;
            }
        }
    }
}

extern "C" void kernel_launch(void* const* d_in, const int* in_sizes, int n_in,
                              void* d_out, int out_size) {
    const float* carry = (const float*)d_in[0];
    const float* x     = (const float*)d_in[1];
    const float* noise = (const float*)d_in[2];
    const float* W0    = (const float*)d_in[3];
    const float* b0    = (const float*)d_in[4];
    const float* W1    = (const float*)d_in[5];
    const float* b1    = (const float*)d_in[6];
    const float* W2    = (const float*)d_in[7];
    const float* b2    = (const float*)d_in[8];
    float* out = (float*)d_out;

    gnsde_kernel<<<BB / MM, NT>>>(carry, x, noise, W0, b0, W1, b1, W2, b2, out);
}

// round 11
// speedup vs baseline: 5.7904x; 1.2572x over previous
#include <cuda_runtime.h>
#include <cstdint>

#define BB 1024
#define TT 2048
#define DD 16
#define UU 4
#define HH 128
#define MM 8
#define NT 256
#define PIT 24          // sIN/sH1/sH2 row pitch (floats); cols 0-7 used (tf32 hi)
#define PPIT 10         // sPart row pitch

typedef unsigned long long u64;

__device__ __forceinline__ uint32_t tf32r(float v) {
    uint32_t r; asm("cvt.rna.tf32.f32 %0, %1;" : "=r"(r) : "f"(v)); return r;
}
__device__ __forceinline__ void split(float w, uint32_t& hi, uint32_t& lo) {
    hi = tf32r(w);
    lo = tf32r(w - __uint_as_float(hi));
}
__device__ __forceinline__ float tanh_fast(float x) {
    float y; asm("tanh.approx.f32 %0, %1;" : "=f"(y) : "f"(x)); return y;
}
__device__ __forceinline__ void mma8(float* d, uint4 a, uint32_t b0, uint32_t b1) {
    asm volatile(
        "mma.sync.aligned.m16n8k8.row.col.f32.tf32.tf32.f32 "
        "{%0,%1,%2,%3}, {%4,%5,%6,%7}, {%8,%9}, {%0,%1,%2,%3};"
        : "+f"(d[0]), "+f"(d[1]), "+f"(d[2]), "+f"(d[3])
        : "r"(a.x), "r"(a.y), "r"(a.z), "r"(a.w), "r"(b0), "r"(b1));
}
__device__ __forceinline__ u64 pku(uint32_t lo, uint32_t hi) {
    return ((u64)hi << 32) | (u64)lo;
}

__global__ void __launch_bounds__(NT, 1)
gnsde_kernel(const float* __restrict__ carry,
             const float* __restrict__ x,
             const float* __restrict__ noise,
             const float* __restrict__ W0,
             const float* __restrict__ b0,
             const float* __restrict__ W1,
             const float* __restrict__ b1,
             const float* __restrict__ W2,
             const float* __restrict__ b2,
             float* __restrict__ out)
{
    __shared__ __align__(16) float sIN[32 * PIT];    // rows k: 0-15 y, 16-19 x, 20-31 zero
    __shared__ __align__(16) float sH1[HH * PIT];
    __shared__ __align__(16) float sH2[HH * PIT];
    __shared__ __align__(16) float sPart[8 * 16 * PPIT];

    const int tid  = threadIdx.x;
    const int wid  = tid >> 5;
    const int lane = tid & 31;
    const int g    = lane >> 2;      // groupID
    const int tg   = lane & 3;       // threadID_in_group
    const int b0r  = blockIdx.x * MM;

    const int r0 = wid * 16 + g;     // A-fragment rows (j / d)
    const int r1 = r0 + 8;

    // ---- persistent weight fragments (2-term: hi + lo of A) ----
    uint4 A1h[16], A1l[16];
#pragma unroll
    for (int c = 0; c < 16; ++c) {
        int k0 = 8 * c + tg, k1 = k0 + 4;
        split(W1[k0 * HH + r0], A1h[c].x, A1l[c].x);
        split(W1[k0 * HH + r1], A1h[c].y, A1l[c].y);
        split(W1[k1 * HH + r0], A1h[c].z, A1l[c].z);
        split(W1[k1 * HH + r1], A1h[c].w, A1l[c].w);
    }
    uint4 A0h[4], A0l[4];
#pragma unroll
    for (int c = 0; c < 4; ++c) {
        int k0 = 8 * c + tg, k1 = k0 + 4;
        float v0 = (k0 < DD + UU) ? W0[k0 * HH + r0] : 0.0f;
        float v1 = (k0 < DD + UU) ? W0[k0 * HH + r1] : 0.0f;
        float v2 = (k1 < DD + UU) ? W0[k1 * HH + r0] : 0.0f;
        float v3 = (k1 < DD + UU) ? W0[k1 * HH + r1] : 0.0f;
        split(v0, A0h[c].x, A0l[c].x);
        split(v1, A0h[c].y, A0l[c].y);
        split(v2, A0h[c].z, A0l[c].z);
        split(v3, A0h[c].w, A0l[c].w);
    }
    uint4 A2h[2], A2l[2];
#pragma unroll
    for (int i = 0; i < 2; ++i) {
        int c = 2 * wid + i;
        int k0 = 8 * c + tg, k1 = k0 + 4;
        split(W2[k0 * DD + g],     A2h[i].x, A2l[i].x);
        split(W2[k0 * DD + g + 8], A2h[i].y, A2l[i].y);
        split(W2[k1 * DD + g],     A2h[i].z, A2l[i].z);
        split(W2[k1 * DD + g + 8], A2h[i].w, A2l[i].w);
    }
    const float b0a = b0[r0], b0b = b0[r1];
    const float b1a = b1[r0], b1b = b1[r1];

    // reduce-phase identity (tid < 128): m = tid>>4, d = tid&15
    const int mR = tid >> 4;
    const int dR = tid & 15;
    const float b2v = b2[dR];
    float yreg = 0.0f;

    // ---- init shared ----
    for (int i = tid; i < 32 * PIT; i += NT) sIN[i] = 0.0f;
    __syncthreads();
    uint32_t* sINu = (uint32_t*)sIN;
    uint32_t* sH1u = (uint32_t*)sH1;
    uint32_t* sH2u = (uint32_t*)sH2;
    if (tid < 128) {
        yreg = carry[(size_t)(b0r + mR) * DD + dR];
        sINu[dR * PIT + mR] = tf32r(yreg);
    }
    if (tid >= 128 && tid < 128 + MM) {
        int m = tid & 7;
        float4 xv = *(const float4*)&x[((size_t)(b0r + m) * TT) * UU];
        float xa[4] = {xv.x, xv.y, xv.z, xv.w};
#pragma unroll
        for (int u = 0; u < 4; ++u)
            sINu[(DD + u) * PIT + m] = tf32r(xa[u]);
    }

    const float alpha = 0.1f;
    const float onema = 0.9f;
    const float sqa   = 0.31622776601683794f;

    for (int t = 0; t < TT; ++t) {
        // ---- prefetch globals ----
        float nz = 0.0f;
        if (tid < 128) nz = noise[((size_t)(b0r + mR) * TT + t) * DD + dR];
        float4 xn = make_float4(0.f, 0.f, 0.f, 0.f);
        const bool xp = (tid >= 128 && tid < 128 + MM) && (t + 1 < TT);
        if (xp) xn = *(const float4*)&x[((size_t)(b0r + (tid & 7)) * TT + (t + 1)) * UU];

        __syncthreads();   // (1) y/x writes of prev step -> L0 reads

        // ===== layer 0: D0 = W0^T(16-slice) @ in, 2-term TF32 =====
        {
            float P[4] = {0, 0, 0, 0}, Q[4] = {0, 0, 0, 0};
#pragma unroll
            for (int c = 0; c < 4; ++c) {
                int rA = 8 * c + tg, rB = rA + 4;
                uint32_t bh0 = sINu[rA * PIT + g];
                uint32_t bh1 = sINu[rB * PIT + g];
                mma8(P, A0h[c], bh0, bh1);
                mma8(Q, A0l[c], bh0, bh1);
            }
            float h0 = tanh_fast(P[0] + Q[0] + b0a);
            float h1 = tanh_fast(P[1] + Q[1] + b0a);
            float h2 = tanh_fast(P[2] + Q[2] + b0b);
            float h3 = tanh_fast(P[3] + Q[3] + b0b);
            *(u64*)&sH1u[r0 * PIT + 2 * tg] = pku(tf32r(h0), tf32r(h1));
            *(u64*)&sH1u[r1 * PIT + 2 * tg] = pku(tf32r(h2), tf32r(h3));
        }
        __syncthreads();   // (2)

        // ===== layer 1: K=128, 16 chunks, 2-term TF32 =====
        {
            float P[4] = {0, 0, 0, 0}, Q[4] = {0, 0, 0, 0};
#pragma unroll
            for (int c = 0; c < 16; ++c) {
                int rA = 8 * c + tg, rB = rA + 4;
                uint32_t bh0 = sH1u[rA * PIT + g];
                uint32_t bh1 = sH1u[rB * PIT + g];
                mma8(P, A1h[c], bh0, bh1);
                mma8(Q, A1l[c], bh0, bh1);
            }
            float h0 = tanh_fast(P[0] + Q[0] + b1a);
            float h1 = tanh_fast(P[1] + Q[1] + b1a);
            float h2 = tanh_fast(P[2] + Q[2] + b1b);
            float h3 = tanh_fast(P[3] + Q[3] + b1b);
            *(u64*)&sH2u[r0 * PIT + 2 * tg] = pku(tf32r(h0), tf32r(h1));
            *(u64*)&sH2u[r1 * PIT + 2 * tg] = pku(tf32r(h2), tf32r(h3));
        }
        __syncthreads();   // (3)

        // ===== layer 2: k-split across warps (chunks 2w, 2w+1), 2-term =====
        {
            float P[4] = {0, 0, 0, 0}, Q[4] = {0, 0, 0, 0};
#pragma unroll
            for (int i = 0; i < 2; ++i) {
                int c = 2 * wid + i;
                int rA = 8 * c + tg, rB = rA + 4;
                uint32_t bh0 = sH2u[rA * PIT + g];
                uint32_t bh1 = sH2u[rB * PIT + g];
                mma8(P, A2h[i], bh0, bh1);
                mma8(Q, A2l[i], bh0, bh1);
            }
            float d0 = P[0] + Q[0];
            float d1 = P[1] + Q[1];
            float d2 = P[2] + Q[2];
            float d3 = P[3] + Q[3];
            *(float2*)&sPart[wid * 160 + g * PPIT + 2 * tg]       = make_float2(d0, d1);
            *(float2*)&sPart[wid * 160 + (g + 8) * PPIT + 2 * tg] = make_float2(d2, d3);
        }
        __syncthreads();   // (4)

        // ===== reduce + gate + outputs: tid<128 = (mR, dR) =====
        if (tid < 128) {
            float s = 0.0f;
#pragma unroll
            for (int w = 0; w < 8; ++w) s += sPart[w * 160 + dR * PPIT + mR];
            float mt = s + b2v;
            float mu = onema * yreg + alpha * mt;
            float yn = mu + sqa * nz;
            size_t base = ((size_t)(b0r + mR) * TT + t) * DD + dR;
            out[base]                        = yn;
            out[base + (size_t)BB * TT * DD] = mt;
            out[base + 2ull * BB * TT * DD]  = mu;
            yreg = yn;
            sINu[dR * PIT + mR] = tf32r(yn);
        } else if (xp) {
            int m = tid & 7;
            float xa[4] = {xn.x, xn.y, xn.z, xn.w};
#pragma unroll
            for (int u = 0; u < 4; ++u)
                sINu[(DD + u) * PIT + m] = tf32r(xa[u]);
        }
    }
}

extern "C" void kernel_launch(void* const* d_in, const int* in_sizes, int n_in,
                              void* d_out, int out_size) {
    const float* carry = (const float*)d_in[0];
    const float* x     = (const float*)d_in[1];
    const float* noise = (const float*)d_in[2];
    const float* W0    = (const float*)d_in[3];
    const float* b0    = (const float*)d_in[4];
    const float* W1    = (const float*)d_in[5];
    const float* b1    = (const float*)d_in[6];
    const float* W2    = (const float*)d_in[7];
    const float* b2    = (const float*)d_in[8];
    float* out = (float*)d_out;

    gnsde_kernel<<<BB / MM, NT>>>(carry, x, noise, W0, b0, W1, b1, W2, b2, out);
}